// round 17
// baseline (speedup 1.0000x reference)
#include <cuda_runtime.h>
#include <cuda_bf16.h>
#include <math.h>

// Problem constants
#define B_TOK   16384
#define D_VIS   768
#define D_LANG  768
#define D_STATE 64
#define D_IN    1600
#define D_MODEL 256
#define N_EXP   4
#define TOPK    2
#define MAXB    518           // max expert blocks after per-bucket padding
#define PERM_N  (MAXB * 32)   // 16576
#define ETH     512           // expert kernel threads (16 warps)

typedef unsigned long long u64;
typedef unsigned int u32;

// ---------------------------------------------------------------------------
// Scratch
// ---------------------------------------------------------------------------
__device__ float g_x[B_TOK * D_MODEL];
__device__ int   g_topidx[B_TOK];             // i0 | (i1<<8)
__device__ float g_topw[B_TOK * 2];
__device__ float g_partial[2048 * 8];
__device__ int   g_bcount[8];                 // per-pair-bucket counts
__device__ int   g_off[8];                    // padded bucket offsets [0..6]
__device__ int   g_pair_slot[B_TOK];          // pid | (slot<<4)
__device__ int   g_perm[PERM_N];              // token index or -1
__device__ unsigned g_done;                   // gate completion ticket

// split-bf16 operands (prepared by prep_kernel each launch; deterministic)
__device__ __align__(16) __nv_bfloat16 g_Ah[B_TOK * D_IN];   // concat(vis,lang,state) hi
__device__ __align__(16) __nv_bfloat16 g_Al[B_TOK * D_IN];   // lo
__device__ __align__(16) __nv_bfloat16 g_Wfh[D_IN * D_MODEL];
__device__ __align__(16) __nv_bfloat16 g_Wfl[D_IN * D_MODEL];
__device__ __align__(16) __nv_bfloat16 g_W1h[4 * 256 * 512];
__device__ __align__(16) __nv_bfloat16 g_W1l[4 * 256 * 512];
__device__ __align__(16) __nv_bfloat16 g_W2h[4 * 512 * 256];
__device__ __align__(16) __nv_bfloat16 g_W2l[4 * 512 * 256];
__device__ __align__(16) __nv_bfloat16 g_W3h[4 * 256 * 256];
__device__ __align__(16) __nv_bfloat16 g_W3l[4 * 256 * 256];

__device__ __forceinline__ float gelu_exact(float v) {
    return 0.5f * v * (1.f + erff(v * 0.70710678118654752f));
}

// ---- cp.async helpers ------------------------------------------------------
__device__ __forceinline__ void cp16(unsigned saddr, const void* g) {
    asm volatile("cp.async.cg.shared.global [%0], [%1], 16;" :: "r"(saddr), "l"(g));
}
__device__ __forceinline__ void cp_commit() { asm volatile("cp.async.commit_group;"); }
__device__ __forceinline__ void cp_wait1()  { asm volatile("cp.async.wait_group 1;"); }
__device__ __forceinline__ void cp_wait0()  { asm volatile("cp.async.wait_group 0;"); }

// ---- tensor-core helpers ---------------------------------------------------
__device__ __forceinline__ void ldsm4(u32& r0, u32& r1, u32& r2, u32& r3, u32 a) {
    asm volatile("ldmatrix.sync.aligned.m8n8.x4.shared.b16 {%0,%1,%2,%3}, [%4];"
                 : "=r"(r0), "=r"(r1), "=r"(r2), "=r"(r3) : "r"(a));
}
__device__ __forceinline__ void ldsm4t(u32& r0, u32& r1, u32& r2, u32& r3, u32 a) {
    asm volatile("ldmatrix.sync.aligned.m8n8.x4.trans.shared.b16 {%0,%1,%2,%3}, [%4];"
                 : "=r"(r0), "=r"(r1), "=r"(r2), "=r"(r3) : "r"(a));
}
__device__ __forceinline__ void mma16816(float* c, u32 a0, u32 a1, u32 a2, u32 a3,
                                         u32 b0, u32 b1) {
    asm volatile(
        "mma.sync.aligned.m16n8k16.row.col.f32.bf16.bf16.f32 "
        "{%0,%1,%2,%3}, {%4,%5,%6,%7}, {%8,%9}, {%0,%1,%2,%3};"
        : "+f"(c[0]), "+f"(c[1]), "+f"(c[2]), "+f"(c[3])
        : "r"(a0), "r"(a1), "r"(a2), "r"(a3), "r"(b0), "r"(b1));
}
__device__ __forceinline__ u32 pack_bf2(float x, float y) {
    __nv_bfloat162 p = __floats2bfloat162_rn(x, y);
    return *(u32*)&p;
}
__device__ __forceinline__ void split_store(char* base_h, char* base_l, int off,
                                            float v0, float v1) {
    float h0f, h1f;
    __nv_bfloat16 h0 = __float2bfloat16(v0); h0f = __bfloat162float(h0);
    __nv_bfloat16 h1 = __float2bfloat16(v1); h1f = __bfloat162float(h1);
    __nv_bfloat162 hp; hp.x = h0; hp.y = h1;
    *(u32*)(base_h + off) = *(u32*)&hp;
    *(u32*)(base_l + off) = pack_bf2(v0 - h0f, v1 - h1f);
}
__device__ __forceinline__ float2 bf2_to_f2(u32 v) {
    __nv_bfloat162 p = *(__nv_bfloat162*)&v;
    return make_float2(__bfloat162float(p.x), __bfloat162float(p.y));
}

extern __shared__ char smemC[];

// ---------------------------------------------------------------------------
// Kernel P: hi/lo split prep for ALL bf16 operands.
// Regions (element index space, total 27,934,720):
//   vis 12,582,912 | lang 12,582,912 | state 1,048,576 -> g_Ah/g_Al [16384][1600]
//   Wf 409,600 | W1 524,288 | W2 524,288 | W3 262,144
// ---------------------------------------------------------------------------
#define PREP_TOTAL 27934720ll

__global__ __launch_bounds__(256) void prep_kernel(
    const float* __restrict__ vis, const float* __restrict__ lang,
    const float* __restrict__ state, const float* __restrict__ Wf,
    const float* __restrict__ W1, const float* __restrict__ W2,
    const float* __restrict__ W3)
{
    const long long stride = (long long)gridDim.x * 256;
    for (long long i = (long long)blockIdx.x * 256 + threadIdx.x;
         i < PREP_TOTAL; i += stride) {
        float v; __nv_bfloat16 *dh, *dl; long long d;
        if (i < 12582912ll) {                  // vis
            long long r = i / 768, c = i - r * 768;
            v = vis[i]; dh = g_Ah; dl = g_Al; d = r * 1600 + c;
        } else if (i < 25165824ll) {           // lang
            long long j = i - 12582912ll;
            long long r = j / 768, c = j - r * 768;
            v = lang[j]; dh = g_Ah; dl = g_Al; d = r * 1600 + 768 + c;
        } else if (i < 26214400ll) {           // state
            long long j = i - 25165824ll;
            long long r = j / 64, c = j - r * 64;
            v = state[j]; dh = g_Ah; dl = g_Al; d = r * 1600 + 1536 + c;
        } else if (i < 26624000ll) {           // Wf
            long long j = i - 26214400ll;
            v = Wf[j]; dh = g_Wfh; dl = g_Wfl; d = j;
        } else if (i < 27148288ll) {           // W1
            long long j = i - 26624000ll;
            v = W1[j]; dh = g_W1h; dl = g_W1l; d = j;
        } else if (i < 27672576ll) {           // W2
            long long j = i - 27148288ll;
            v = W2[j]; dh = g_W2h; dl = g_W2l; d = j;
        } else {                               // W3
            long long j = i - 27672576ll;
            v = W3[j]; dh = g_W3h; dl = g_W3l; d = j;
        }
        __nv_bfloat16 h = __float2bfloat16(v);
        dh[d] = h;
        dl[d] = __float2bfloat16(v - __bfloat162float(h));
    }
}

// ---------------------------------------------------------------------------
// Kernel A: fusion on TENSOR CORES, pre-split operands via pure cp.async
// double buffer (no in-kernel conversion). Fragment math identical to the
// validated round-11 kernel. 64 rows x 256 cols per block, 50 k32 stages.
// ---------------------------------------------------------------------------
#define FA_H   0
#define FA_L   5120
#define FB_H   10240
#define FB_L   27136
#define FSTAGE 44032
#define FAS    80      // A row stride bytes (40 bf16)
#define FBS    528     // B row stride bytes (264 bf16)

__global__ __launch_bounds__(256, 1) void fusion_kernel(
    const float* __restrict__ bf, const float* __restrict__ gf,
    const float* __restrict__ bfln)
{
    __shared__ float ln_s[64][2];
    __shared__ float ln_q[64][2];

    const int tid = threadIdx.x, lane = tid & 31, wid = tid >> 5;
    const int mgrp = wid >> 1, ngrp = wid & 1;     // 4 mgrp x 2 ngrp
    const int q = lane >> 3, lr = lane & 7;
    const int arow = (q & 1) * 8 + lr;
    const int acol8 = (q >> 1) * 8;
    const int lrow = lane >> 2, lcol2 = (lane & 3) * 2;
    const int row0 = blockIdx.x * 64;

    if (blockIdx.x == 0 && tid < 8) g_bcount[tid] = 0;   // reset gate atomics
    if (blockIdx.x < 65) {                               // init perm for scatter
        int i = blockIdx.x * 256 + tid;
        if (i < PERM_N) g_perm[i] = -1;
    }

    const unsigned su = (unsigned)__cvta_generic_to_shared(smemC);

    float acc[16][4];
#pragma unroll
    for (int t8 = 0; t8 < 16; t8++)
#pragma unroll
        for (int j = 0; j < 4; j++) acc[t8][j] = 0.f;

    auto issue_tile = [&](int t, int buf) {
        unsigned sb = su + buf * FSTAGE;
        const size_t abase = (size_t)row0 * 1600 + t * 32;
        {   // A: 64x32 bf16 hi+lo, 1 cp16 each per thread
            int r = tid >> 2, c = (tid & 3) * 8;
            cp16(sb + FA_H + r * FAS + c * 2, g_Ah + abase + (size_t)r * 1600 + c);
            cp16(sb + FA_L + r * FAS + c * 2, g_Al + abase + (size_t)r * 1600 + c);
        }
#pragma unroll
        for (int i = 0; i < 4; i++) {   // B: 32x256 bf16 hi+lo
            int idx = tid + i * 256;
            int r = idx >> 5, c = (idx & 31) * 8;
            cp16(sb + FB_H + r * FBS + c * 2, g_Wfh + (size_t)(t * 32 + r) * 256 + c);
            cp16(sb + FB_L + r * FBS + c * 2, g_Wfl + (size_t)(t * 32 + r) * 256 + c);
        }
        cp_commit();
    };

    issue_tile(0, 0);
#pragma unroll 1
    for (int s = 0; s < 50; s++) {
        if (s + 1 < 50) { issue_tile(s + 1, (s + 1) & 1); cp_wait1(); }
        else cp_wait0();
        __syncthreads();
        unsigned sb = su + (s & 1) * FSTAGE;
#pragma unroll
        for (int ksub = 0; ksub < 2; ksub++) {
            u32 ah0, ah1, ah2, ah3, al0, al1, al2, al3;
            u32 aaddr = sb + FA_H + (mgrp * 16 + arow) * FAS + (ksub * 16 + acol8) * 2;
            ldsm4(ah0, ah1, ah2, ah3, aaddr);
            ldsm4(al0, al1, al2, al3, aaddr + (FA_L - FA_H));
#pragma unroll
            for (int t = 0; t < 8; t++) {
                int nb = ngrp * 128 + t * 16;
                u32 baddr = sb + FB_H + (ksub * 16 + arow) * FBS + (nb + acol8) * 2;
                u32 bh0, bh1, bh2, bh3, bl0, bl1, bl2, bl3;
                ldsm4t(bh0, bh1, bh2, bh3, baddr);
                ldsm4t(bl0, bl1, bl2, bl3, baddr + (FB_L - FB_H));
                mma16816(acc[2 * t],     ah0, ah1, ah2, ah3, bh0, bh1);
                mma16816(acc[2 * t],     ah0, ah1, ah2, ah3, bl0, bl1);
                mma16816(acc[2 * t],     al0, al1, al2, al3, bh0, bh1);
                mma16816(acc[2 * t + 1], ah0, ah1, ah2, ah3, bh2, bh3);
                mma16816(acc[2 * t + 1], ah0, ah1, ah2, ah3, bl2, bl3);
                mma16816(acc[2 * t + 1], al0, al1, al2, al3, bh2, bh3);
            }
        }
        __syncthreads();
    }

    {
        int rA = mgrp * 16 + lrow, rB = rA + 8;
        float sA = 0.f, qA = 0.f, sB = 0.f, qB = 0.f;
#pragma unroll
        for (int t8 = 0; t8 < 16; t8++) {
            int col = ngrp * 128 + t8 * 8 + lcol2;
            float bb0 = bf[col], bb1 = bf[col + 1];
            acc[t8][0] += bb0; acc[t8][1] += bb1;
            acc[t8][2] += bb0; acc[t8][3] += bb1;
            sA += acc[t8][0] + acc[t8][1];
            qA += acc[t8][0] * acc[t8][0] + acc[t8][1] * acc[t8][1];
            sB += acc[t8][2] + acc[t8][3];
            qB += acc[t8][2] * acc[t8][2] + acc[t8][3] * acc[t8][3];
        }
#pragma unroll
        for (int o = 1; o <= 2; o <<= 1) {
            sA += __shfl_xor_sync(0xffffffffu, sA, o);
            qA += __shfl_xor_sync(0xffffffffu, qA, o);
            sB += __shfl_xor_sync(0xffffffffu, sB, o);
            qB += __shfl_xor_sync(0xffffffffu, qB, o);
        }
        if ((lane & 3) == 0) {
            ln_s[rA][ngrp] = sA; ln_q[rA][ngrp] = qA;
            ln_s[rB][ngrp] = sB; ln_q[rB][ngrp] = qB;
        }
        __syncthreads();
        float smA = ln_s[rA][0] + ln_s[rA][1];
        float sqA = ln_q[rA][0] + ln_q[rA][1];
        float smB = ln_s[rB][0] + ln_s[rB][1];
        float sqB = ln_q[rB][0] + ln_q[rB][1];
        float muA = smA * (1.f / 256.f);
        float rstdA = rsqrtf(sqA * (1.f / 256.f) - muA * muA + 1e-5f);
        float muB = smB * (1.f / 256.f);
        float rstdB = rsqrtf(sqB * (1.f / 256.f) - muB * muB + 1e-5f);
#pragma unroll
        for (int t8 = 0; t8 < 16; t8++) {
            int col = ngrp * 128 + t8 * 8 + lcol2;
            float g0 = gf[col], g1 = gf[col + 1];
            float l0 = bfln[col], l1 = bfln[col + 1];
            float y0 = gelu_exact(g0 * (acc[t8][0] - muA) * rstdA + l0);
            float y1 = gelu_exact(g1 * (acc[t8][1] - muA) * rstdA + l1);
            float y2 = gelu_exact(g0 * (acc[t8][2] - muB) * rstdB + l0);
            float y3 = gelu_exact(g1 * (acc[t8][3] - muB) * rstdB + l1);
            *(float2*)&g_x[(size_t)(row0 + rA) * 256 + col] = make_float2(y0, y1);
            *(float2*)&g_x[(size_t)(row0 + rB) * 256 + col] = make_float2(y2, y3);
        }
    }
}

// ---------------------------------------------------------------------------
// Kernel B: gate + top-2 + buckets + lb-loss partials (split prep removed)
// ---------------------------------------------------------------------------
__global__ __launch_bounds__(256) void gate_kernel(const float* __restrict__ Wg)
{
    const int tid = threadIdx.x, lane = tid & 31, w = tid >> 5;
    const int t = blockIdx.x * 8 + w;

    float p0 = 0.f, p1 = 0.f, p2 = 0.f, p3 = 0.f;
    const float* xr = g_x + (size_t)t * D_MODEL;
#pragma unroll
    for (int j = 0; j < 8; j++) {
        int c = lane + 32 * j;
        float xv = xr[c];
        float4 wg = *(const float4*)(Wg + c * 4);
        p0 = fmaf(xv, wg.x, p0); p1 = fmaf(xv, wg.y, p1);
        p2 = fmaf(xv, wg.z, p2); p3 = fmaf(xv, wg.w, p3);
    }
#pragma unroll
    for (int off = 16; off; off >>= 1) {
        p0 += __shfl_xor_sync(0xffffffffu, p0, off);
        p1 += __shfl_xor_sync(0xffffffffu, p1, off);
        p2 += __shfl_xor_sync(0xffffffffu, p2, off);
        p3 += __shfl_xor_sync(0xffffffffu, p3, off);
    }

    __shared__ float sprob[8][4];
    __shared__ float scnt[8][4];
    if (lane == 0) {
        float l[4] = {p0, p1, p2, p3};
        float mx = fmaxf(fmaxf(l[0], l[1]), fmaxf(l[2], l[3]));
        float e[4], se = 0.f;
#pragma unroll
        for (int i = 0; i < 4; i++) { e[i] = expf(l[i] - mx); se += e[i]; }
        float inv = 1.f / se;
#pragma unroll
        for (int i = 0; i < 4; i++) sprob[w][i] = e[i] * inv;

        int i0 = 0;
#pragma unroll
        for (int i = 1; i < 4; i++) if (l[i] > l[i0]) i0 = i;
        int i1 = -1;
#pragma unroll
        for (int i = 0; i < 4; i++) {
            if (i == i0) continue;
            if (i1 < 0 || l[i] > l[i1]) i1 = i;
        }
        float w0 = 1.f / (1.f + expf(l[i1] - l[i0]));
        g_topidx[t] = i0 | (i1 << 8);
        g_topw[2 * t]     = w0;
        g_topw[2 * t + 1] = 1.f - w0;
#pragma unroll
        for (int i = 0; i < 4; i++) scnt[w][i] = (i == i0 || i == i1) ? 1.f : 0.f;

        int a = min(i0, i1), b = max(i0, i1);
        int pid = (a * (7 - a)) / 2 + (b - a - 1);
        int slot = atomicAdd(&g_bcount[pid], 1);
        g_pair_slot[t] = pid | (slot << 4);
    }
    __syncthreads();
    if (tid < 4) {
        float s = 0.f;
        for (int ww = 0; ww < 8; ww++) s += sprob[ww][tid];
        g_partial[blockIdx.x * 8 + tid] = s;
    } else if (tid < 8) {
        int e = tid - 4;
        float s = 0.f;
        for (int ww = 0; ww < 8; ww++) s += scnt[ww][e];
        g_partial[blockIdx.x * 8 + tid] = s;
    }
    __syncthreads();
    if (tid == 0) {
        __threadfence();
        unsigned ticket = atomicAdd(&g_done, 1u);
        if (ticket == gridDim.x - 1) {
            g_done = 0;
            __threadfence();
            int o = 0;
#pragma unroll
            for (int p = 0; p < 6; p++) {
                g_off[p] = o;
                o += (g_bcount[p] + 31) & ~31;
            }
            g_off[6] = o;
        }
    }
}

// ---------------------------------------------------------------------------
// Kernel B3: scatter (blocks 0-63) + loss reduction (block 64)
// ---------------------------------------------------------------------------
__global__ __launch_bounds__(256) void scatter_kernel(float* __restrict__ out,
                                                      int out_size)
{
    if (blockIdx.x < 64) {
        int t = blockIdx.x * 256 + threadIdx.x;
        if (t < B_TOK) {
            int ps = g_pair_slot[t];
            int pid = ps & 15, slot = ps >> 4;
            g_perm[g_off[pid] + slot] = t;
        }
        return;
    }
    // block 64: deterministic lb-loss reduction
    __shared__ float sh[256];
    __shared__ float totals[8];
    int tid = threadIdx.x;
    float acc[8];
#pragma unroll
    for (int f = 0; f < 8; f++) acc[f] = 0.f;
    for (int i = tid; i < 2048; i += 256) {
#pragma unroll
        for (int f = 0; f < 8; f++) acc[f] += g_partial[i * 8 + f];
    }
    for (int f = 0; f < 8; f++) {
        sh[tid] = acc[f];
        __syncthreads();
        for (int s = 128; s > 0; s >>= 1) {
            if (tid < s) sh[tid] += sh[tid + s];
            __syncthreads();
        }
        if (tid == 0) totals[f] = sh[0];
        __syncthreads();
    }
    if (tid == 0 && out_size > B_TOK * D_MODEL) {
        float loss = 0.f;
#pragma unroll
        for (int i = 0; i < 4; i++) {
            float f_i = totals[4 + i] / (float)(B_TOK * TOPK);
            float pm  = totals[i] / (float)B_TOK;
            loss += f_i * pm;
        }
        out[B_TOK * D_MODEL] = (float)N_EXP * loss;
    }
}

// ---------------------------------------------------------------------------
// Kernel C: bucketed expert chain on TENSOR CORES — UNCHANGED from round 15
// (measured best: 353us). 512 threads, 2 mgrp x 8 ngrp.
// ---------------------------------------------------------------------------
#define X_H   0
#define X_L   16896
#define H1_H  33792
#define H1_L  67072
#define H2_H  100352
#define H2_L  117248
#define RINGO 134144
#define STAGE 33792
#define XS    528
#define H1S   1040
#define WS1   1040
#define WS2   528

__global__ __launch_bounds__(ETH, 1) void expert_kernel(
    const float* __restrict__ b1, const float* __restrict__ b2,
    const float* __restrict__ b3,
    const float* __restrict__ eg, const float* __restrict__ eb,
    float* __restrict__ out)
{
    __shared__ int   s_tok[32];
    __shared__ float ln_s[32][8];
    __shared__ float ln_q[32][8];

    const int tid = threadIdx.x, lane = tid & 31, wid = tid >> 5;
    const int mgrp = wid >> 3, ngrp = wid & 7;      // 2 x 8
    const int q = lane >> 3, lr = lane & 7;
    const int lrow = lane >> 2, lcol2 = (lane & 3) * 2;
    const int base = blockIdx.x * 32;

    int off6 = g_off[6];
    if (base >= off6) return;
    int pid = 0;
#pragma unroll
    for (int p = 0; p < 5; p++) if (base >= g_off[p + 1]) pid = p + 1;
    const int pe0[6] = {0, 0, 0, 1, 1, 2};
    const int pe1[6] = {1, 2, 3, 2, 3, 3};
    const int e0 = pe0[pid], e1 = pe1[pid];

    if (tid < 32) s_tok[tid] = g_perm[base + tid];
    __syncthreads();

    const unsigned su = (unsigned)__cvta_generic_to_shared(smemC);

    // gather x + split (2048 float4, 4 per thread)
#pragma unroll
    for (int i = 0; i < 4; i++) {
        int idx = tid + i * ETH;
        int r = idx >> 6, c4 = (idx & 63) << 2;
        int tk = s_tok[r]; if (tk < 0) tk = 0;
        float4 v = *(const float4*)(g_x + (size_t)tk * 256 + c4);
        int off = r * XS + c4 * 2;
        split_store(smemC + X_H, smemC + X_L, off,     v.x, v.y);
        split_store(smemC + X_H, smemC + X_L, off + 4, v.z, v.w);
    }

    float oacc[4][4];
#pragma unroll
    for (int t8 = 0; t8 < 4; t8++)
#pragma unroll
        for (int j = 0; j < 4; j++) oacc[t8][j] = 0.f;
    __syncthreads();

    const int arow = (q & 1) * 8 + lr;
    const int acol8 = (q >> 1) * 8;

#pragma unroll 1
    for (int ei = 0; ei < 2; ei++) {
        const int e = ei ? e1 : e0;

        // ================= GEMM1: h1 = gelu(x @ W1[e] + b1)  K=256, N=512
        {
            const __nv_bfloat16* Gh = g_W1h + (size_t)e * 131072;
            const __nv_bfloat16* Gl = g_W1l + (size_t)e * 131072;
            float acc[8][4];
#pragma unroll
            for (int t8 = 0; t8 < 8; t8++)
#pragma unroll
                for (int j = 0; j < 4; j++) acc[t8][j] = 0.f;

            auto stage_g1 = [&](int s, int buf) {
                unsigned sb = su + RINGO + buf * STAGE;
                const __nv_bfloat16* gh = Gh + s * 16 * 512;
                const __nv_bfloat16* gl = Gl + s * 16 * 512;
#pragma unroll
                for (int i = 0; i < 2; i++) {
                    int c = tid + i * ETH; int r = c >> 6, c16 = c & 63;
                    cp16(sb + r * WS1 + c16 * 16, gh + r * 512 + c16 * 8);
                }
#pragma unroll
                for (int i = 0; i < 2; i++) {
                    int c = tid + i * ETH; int r = c >> 6, c16 = c & 63;
                    cp16(sb + 16640 + r * WS1 + c16 * 16, gl + r * 512 + c16 * 8);
                }
                cp_commit();
            };

            stage_g1(0, 0);
#pragma unroll 1
            for (int s = 0; s < 16; s++) {
                if (s + 1 < 16) { stage_g1(s + 1, (s + 1) & 1); cp_wait1(); }
                else cp_wait0();
                __syncthreads();
                unsigned wb = su + RINGO + (s & 1) * STAGE;
                u32 ah0, ah1, ah2, ah3, al0, al1, al2, al3;
                u32 aaddr = su + X_H + (mgrp * 16 + arow) * XS + (s * 16 + acol8) * 2;
                ldsm4(ah0, ah1, ah2, ah3, aaddr);
                ldsm4(al0, al1, al2, al3, aaddr + (X_L - X_H));
#pragma unroll
                for (int t = 0; t < 4; t++) {
                    int nb = ngrp * 64 + t * 16;
                    u32 baddr = wb + arow * WS1 + (nb + acol8) * 2;
                    u32 bh0, bh1, bh2, bh3, bl0, bl1, bl2, bl3;
                    ldsm4t(bh0, bh1, bh2, bh3, baddr);
                    ldsm4t(bl0, bl1, bl2, bl3, baddr + 16640);
                    mma16816(acc[2 * t],     ah0, ah1, ah2, ah3, bh0, bh1);
                    mma16816(acc[2 * t],     ah0, ah1, ah2, ah3, bl0, bl1);
                    mma16816(acc[2 * t],     al0, al1, al2, al3, bh0, bh1);
                    mma16816(acc[2 * t + 1], ah0, ah1, ah2, ah3, bh2, bh3);
                    mma16816(acc[2 * t + 1], ah0, ah1, ah2, ah3, bl2, bl3);
                    mma16816(acc[2 * t + 1], al0, al1, al2, al3, bh2, bh3);
                }
                __syncthreads();
            }
#pragma unroll
            for (int t8 = 0; t8 < 8; t8++) {
                int col = ngrp * 64 + t8 * 8 + lcol2;
                int rA = mgrp * 16 + lrow;
                float bb0 = b1[e * 512 + col], bb1 = b1[e * 512 + col + 1];
                split_store(smemC + H1_H, smemC + H1_L, rA * H1S + col * 2,
                            gelu_exact(acc[t8][0] + bb0), gelu_exact(acc[t8][1] + bb1));
                split_store(smemC + H1_H, smemC + H1_L, (rA + 8) * H1S + col * 2,
                            gelu_exact(acc[t8][2] + bb0), gelu_exact(acc[t8][3] + bb1));
            }
            __syncthreads();
        }

        // ================= GEMM2: h2 = gelu(h1 @ W2[e] + b2)  K=512, N=256
        {
            const __nv_bfloat16* Gh = g_W2h + (size_t)e * 131072;
            const __nv_bfloat16* Gl = g_W2l + (size_t)e * 131072;
            float acc[4][4];
#pragma unroll
            for (int t8 = 0; t8 < 4; t8++)
#pragma unroll
                for (int j = 0; j < 4; j++) acc[t8][j] = 0.f;

            auto stage_g23 = [&](const __nv_bfloat16* gh, const __nv_bfloat16* gl,
                                 int s, int buf) {
                unsigned sb = su + RINGO + buf * STAGE;
                const __nv_bfloat16* ph = gh + s * 32 * 256;
                const __nv_bfloat16* pl = gl + s * 32 * 256;
#pragma unroll
                for (int i = 0; i < 2; i++) {
                    int c = tid + i * ETH; int r = c >> 5, c16 = c & 31;
                    cp16(sb + r * WS2 + c16 * 16, ph + r * 256 + c16 * 8);
                }
#pragma unroll
                for (int i = 0; i < 2; i++) {
                    int c = tid + i * ETH; int r = c >> 5, c16 = c & 31;
                    cp16(sb + 16896 + r * WS2 + c16 * 16, pl + r * 256 + c16 * 8);
                }
                cp_commit();
            };

            stage_g23(Gh, Gl, 0, 0);
#pragma unroll 1
            for (int s = 0; s < 16; s++) {
                if (s + 1 < 16) { stage_g23(Gh, Gl, s + 1, (s + 1) & 1); cp_wait1(); }
                else cp_wait0();
                __syncthreads();
                unsigned wb = su + RINGO + (s & 1) * STAGE;
#pragma unroll
                for (int sub = 0; sub < 2; sub++) {
                    int k0 = s * 32 + sub * 16;
                    u32 ah0, ah1, ah2, ah3, al0, al1, al2, al3;
                    u32 aaddr = su + H1_H + (mgrp * 16 + arow) * H1S + (k0 + acol8) * 2;
                    ldsm4(ah0, ah1, ah2, ah3, aaddr);
                    ldsm4(al0, al1, al2, al3, aaddr + (H1_L - H1_H));
#pragma unroll
                    for (int t = 0; t < 2; t++) {
                        int nb = ngrp * 32 + t * 16;
                        u32 baddr = wb + (sub * 16 + arow) * WS2 + (nb + acol8) * 2;
                        u32 bh0, bh1, bh2, bh3, bl0, bl1, bl2, bl3;
                        ldsm4t(bh0, bh1, bh2, bh3, baddr);
                        ldsm4t(bl0, bl1, bl2, bl3, baddr + 16896);
                        mma16816(acc[2 * t],     ah0, ah1, ah2, ah3, bh0, bh1);
                        mma16816(acc[2 * t],     ah0, ah1, ah2, ah3, bl0, bl1);
                        mma16816(acc[2 * t],     al0, al1, al2, al3, bh0, bh1);
                        mma16816(acc[2 * t + 1], ah0, ah1, ah2, ah3, bh2, bh3);
                        mma16816(acc[2 * t + 1], ah0, ah1, ah2, ah3, bl2, bl3);
                        mma16816(acc[2 * t + 1], al0, al1, al2, al3, bh2, bh3);
                    }
                }
                __syncthreads();
            }
#pragma unroll
            for (int t8 = 0; t8 < 4; t8++) {
                int col = ngrp * 32 + t8 * 8 + lcol2;
                int rA = mgrp * 16 + lrow;
                float bb0 = b2[e * 256 + col], bb1 = b2[e * 256 + col + 1];
                split_store(smemC + H2_H, smemC + H2_L, rA * XS + col * 2,
                            gelu_exact(acc[t8][0] + bb0), gelu_exact(acc[t8][1] + bb1));
                split_store(smemC + H2_H, smemC + H2_L, (rA + 8) * XS + col * 2,
                            gelu_exact(acc[t8][2] + bb0), gelu_exact(acc[t8][3] + bb1));
            }
            __syncthreads();
        }

        // ================= GEMM3: h3 = h2 @ W3[e] + b3  K=256, N=256
        float acc3[4][4];
#pragma unroll
        for (int t8 = 0; t8 < 4; t8++)
#pragma unroll
            for (int j = 0; j < 4; j++) acc3[t8][j] = 0.f;
        {
            const __nv_bfloat16* Gh = g_W3h + (size_t)e * 65536;
            const __nv_bfloat16* Gl = g_W3l + (size_t)e * 65536;
            auto stage_g3 = [&](int s, int buf) {
                unsigned sb = su + RINGO + buf * STAGE;
                const __nv_bfloat16* ph = Gh + s * 32 * 256;
                const __nv_bfloat16* pl = Gl + s * 32 * 256;
#pragma unroll
                for (int i = 0; i < 2; i++) {
                    int c = tid + i * ETH; int r = c >> 5, c16 = c & 31;
                    cp16(sb + r * WS2 + c16 * 16, ph + r * 256 + c16 * 8);
                }
#pragma unroll
                for (int i = 0; i < 2; i++) {
                    int c = tid + i * ETH; int r = c >> 5, c16 = c & 31;
                    cp16(sb + 16896 + r * WS2 + c16 * 16, pl + r * 256 + c16 * 8);
                }
                cp_commit();
            };

            stage_g3(0, 0);
#pragma unroll 1
            for (int s = 0; s < 8; s++) {
                if (s + 1 < 8) { stage_g3(s + 1, (s + 1) & 1); cp_wait1(); }
                else cp_wait0();
                __syncthreads();
                unsigned wb = su + RINGO + (s & 1) * STAGE;
#pragma unroll
                for (int sub = 0; sub < 2; sub++) {
                    int k0 = s * 32 + sub * 16;
                    u32 ah0, ah1, ah2, ah3, al0, al1, al2, al3;
                    u32 aaddr = su + H2_H + (mgrp * 16 + arow) * XS + (k0 + acol8) * 2;
                    ldsm4(ah0, ah1, ah2, ah3, aaddr);
                    ldsm4(al0, al1, al2, al3, aaddr + (H2_L - H2_H));
#pragma unroll
                    for (int t = 0; t < 2; t++) {
                        int nb = ngrp * 32 + t * 16;
                        u32 baddr = wb + (sub * 16 + arow) * WS2 + (nb + acol8) * 2;
                        u32 bh0, bh1, bh2, bh3, bl0, bl1, bl2, bl3;
                        ldsm4t(bh0, bh1, bh2, bh3, baddr);
                        ldsm4t(bl0, bl1, bl2, bl3, baddr + 16896);
                        mma16816(acc3[2 * t],     ah0, ah1, ah2, ah3, bh0, bh1);
                        mma16816(acc3[2 * t],     ah0, ah1, ah2, ah3, bl0, bl1);
                        mma16816(acc3[2 * t],     al0, al1, al2, al3, bh0, bh1);
                        mma16816(acc3[2 * t + 1], ah0, ah1, ah2, ah3, bh2, bh3);
                        mma16816(acc3[2 * t + 1], ah0, ah1, ah2, ah3, bl2, bl3);
                        mma16816(acc3[2 * t + 1], al0, al1, al2, al3, bh2, bh3);
                    }
                }
                __syncthreads();
            }
        }

        // ================= Epilogue: LN(x + h3), weighted accumulate
        {
            int rA = mgrp * 16 + lrow, rB = rA + 8;
            float sA = 0.f, qA = 0.f, sB = 0.f, qB = 0.f;
#pragma unroll
            for (int t8 = 0; t8 < 4; t8++) {
                int col = ngrp * 32 + t8 * 8 + lcol2;
                float bb0 = b3[e * 256 + col], bb1 = b3[e * 256 + col + 1];
                float2 xa = bf2_to_f2(*(u32*)(smemC + X_H + rA * XS + col * 2));
                float2 xal = bf2_to_f2(*(u32*)(smemC + X_L + rA * XS + col * 2));
                float2 xb = bf2_to_f2(*(u32*)(smemC + X_H + rB * XS + col * 2));
                float2 xbl = bf2_to_f2(*(u32*)(smemC + X_L + rB * XS + col * 2));
                float v0 = acc3[t8][0] + bb0 + xa.x + xal.x;
                float v1 = acc3[t8][1] + bb1 + xa.y + xal.y;
                float v2 = acc3[t8][2] + bb0 + xb.x + xbl.x;
                float v3 = acc3[t8][3] + bb1 + xb.y + xbl.y;
                acc3[t8][0] = v0; acc3[t8][1] = v1; acc3[t8][2] = v2; acc3[t8][3] = v3;
                sA += v0 + v1; qA += v0 * v0 + v1 * v1;
                sB += v2 + v3; qB += v2 * v2 + v3 * v3;
            }
#pragma unroll
            for (int o = 1; o <= 2; o <<= 1) {
                sA += __shfl_xor_sync(0xffffffffu, sA, o);
                qA += __shfl_xor_sync(0xffffffffu, qA, o);
                sB += __shfl_xor_sync(0xffffffffu, sB, o);
                qB += __shfl_xor_sync(0xffffffffu, qB, o);
            }
            if ((lane & 3) == 0) {
                ln_s[rA][ngrp] = sA; ln_q[rA][ngrp] = qA;
                ln_s[rB][ngrp] = sB; ln_q[rB][ngrp] = qB;
            }
            __syncthreads();
            float smA = 0.f, sqA = 0.f, smB = 0.f, sqB = 0.f;
#pragma unroll
            for (int j = 0; j < 8; j++) {
                smA += ln_s[rA][j]; sqA += ln_q[rA][j];
                smB += ln_s[rB][j]; sqB += ln_q[rB][j];
            }
            float muA = smA * (1.f / 256.f);
            float rstdA = rsqrtf(sqA * (1.f / 256.f) - muA * muA + 1e-5f);
            float muB = smB * (1.f / 256.f);
            float rstdB = rsqrtf(sqB * (1.f / 256.f) - muB * muB + 1e-5f);
            float wsA = 0.f, wsB = 0.f;
            {
                int tk = s_tok[rA];
                if (tk >= 0) {
                    int ip = g_topidx[tk];
                    wsA = (e == (ip & 0xff)) ? g_topw[2 * tk] : g_topw[2 * tk + 1];
                }
                tk = s_tok[rB];
                if (tk >= 0) {
                    int ip = g_topidx[tk];
                    wsB = (e == (ip & 0xff)) ? g_topw[2 * tk] : g_topw[2 * tk + 1];
                }
            }
#pragma unroll
            for (int t8 = 0; t8 < 4; t8++) {
                int col = ngrp * 32 + t8 * 8 + lcol2;
                float eg0 = eg[e * 256 + col], eg1 = eg[e * 256 + col + 1];
                float eb0 = eb[e * 256 + col], eb1 = eb[e * 256 + col + 1];
                oacc[t8][0] += wsA * (eg0 * (acc3[t8][0] - muA) * rstdA + eb0);
                oacc[t8][1] += wsA * (eg1 * (acc3[t8][1] - muA) * rstdA + eb1);
                oacc[t8][2] += wsB * (eg0 * (acc3[t8][2] - muB) * rstdB + eb0);
                oacc[t8][3] += wsB * (eg1 * (acc3[t8][3] - muB) * rstdB + eb1);
            }
            __syncthreads();
        }
    }

    // store
    {
        int rA = mgrp * 16 + lrow, rB = rA + 8;
        int tkA = s_tok[rA], tkB = s_tok[rB];
#pragma unroll
        for (int t8 = 0; t8 < 4; t8++) {
            int col = ngrp * 32 + t8 * 8 + lcol2;
            if (tkA >= 0)
                *(float2*)&out[(size_t)tkA * 256 + col] =
                    make_float2(oacc[t8][0], oacc[t8][1]);
            if (tkB >= 0)
                *(float2*)&out[(size_t)tkB * 256 + col] =
                    make_float2(oacc[t8][2], oacc[t8][3]);
        }
    }
}

// ---------------------------------------------------------------------------
extern "C" void kernel_launch(void* const* d_in, const int* in_sizes, int n_in,
                              void* d_out, int out_size)
{
    const float* vis   = (const float*)d_in[0];
    const float* lang  = (const float*)d_in[1];
    const float* state = (const float*)d_in[2];
    const float* Wf    = (const float*)d_in[3];
    const float* bf    = (const float*)d_in[4];
    const float* gf    = (const float*)d_in[5];
    const float* bfln  = (const float*)d_in[6];
    const float* Wg    = (const float*)d_in[7];
    const float* W1    = (const float*)d_in[8];
    const float* b1    = (const float*)d_in[9];
    const float* W2    = (const float*)d_in[10];
    const float* b2    = (const float*)d_in[11];
    const float* W3    = (const float*)d_in[12];
    const float* b3    = (const float*)d_in[13];
    const float* eg    = (const float*)d_in[14];
    const float* eb    = (const float*)d_in[15];
    float* out = (float*)d_out;

    cudaFuncSetAttribute(fusion_kernel,
                         cudaFuncAttributeMaxDynamicSharedMemorySize, 88064);
    cudaFuncSetAttribute(expert_kernel,
                         cudaFuncAttributeMaxDynamicSharedMemorySize, 201728);

    prep_kernel<<<4096, 256>>>(vis, lang, state, Wf, W1, W2, W3);
    fusion_kernel<<<B_TOK / 64, 256, 88064>>>(bf, gf, bfln);
    gate_kernel<<<B_TOK / 8, 256>>>(Wg);
    scatter_kernel<<<65, 256>>>(out, out_size);       // + loss (block 64)
    expert_kernel<<<MAXB, ETH, 201728>>>(b1, b2, b3, eg, eb, out);
}